// round 13
// baseline (speedup 1.0000x reference)
#include <cuda_runtime.h>

#define T_STEPS 64
#define BATCH   32768
#define NCBLK   256
#define BLK     256
#define CHUNK   8
#define FULLM   0xffffffffu

// Coefficient layout: [t][p][w] float2, p = row-pair 0..2, w = 0..15
//   w 0-5 : (M[2p][w],   M[2p+1][w])      -- multiplies m[w]
//   w 6-11: (N[2p][w-6], N[2p+1][w-6])    -- multiplies u[w-6]
//   w 12-14:(K[2p][w-12],K[2p+1][w-12])   -- multiplies z[w-12]
//   w 15  : pad (zero-filled by producer)
__device__ __align__(16) float2 g_coef2[T_STEPS * 48];
__device__ int g_flag;

__global__ void reset_kernel() { g_flag = 0; }

// ---------------- f32x2 helpers ----------------
__device__ __forceinline__ unsigned long long pack2(float lo, float hi) {
    unsigned long long r;
    asm("mov.b64 %0, {%1, %2};" : "=l"(r) : "f"(lo), "f"(hi));
    return r;
}
__device__ __forceinline__ void unpack2(float& lo, float& hi, unsigned long long v) {
    asm("mov.b64 {%0, %1}, %2;" : "=f"(lo), "=f"(hi) : "l"(v));
}
__device__ __forceinline__ unsigned long long fma2(unsigned long long a,
                                                   unsigned long long b,
                                                   unsigned long long c) {
    unsigned long long d;
    asm("fma.rn.f32x2 %0, %1, %2, %3;" : "=l"(d) : "l"(a), "l"(b), "l"(c));
    return d;
}
__device__ __forceinline__ unsigned long long add2(unsigned long long a,
                                                   unsigned long long b) {
    unsigned long long d;
    asm("add.rn.f32x2 %0, %1, %2;" : "=l"(d) : "l"(a), "l"(b));
    return d;
}

__global__ void __launch_bounds__(BLK)
fused_kernel(const float* __restrict__ meas,
             const float* __restrict__ useq,
             const float* __restrict__ mean0,
             const float* __restrict__ cov0,
             const float* __restrict__ gA,
             const float* __restrict__ gBm,
             const float* __restrict__ gQt,
             const float* __restrict__ gC,
             const float* __restrict__ gRt,
             float* __restrict__ out)
{
    __shared__ float sA[36], sC[18], sAP[36], sCP[18];
    __shared__ __align__(16) float scf[CHUNK * 96];

    if (blockIdx.x == 0) {
        // ================= PRODUCER: spill-free smem-transpose Riccati =================
        if (threadIdx.x >= 32) return;
        const int lane = threadIdx.x;
        const int jc = lane < 6 ? lane : 5;

        for (int e = lane; e < 36; e += 32) sA[e] = gA[e];
        for (int e = lane; e < 18; e += 32) sC[e] = gC[e];
        __syncwarp();

        float Acol[6], Bmcol[6], Qcol[6], Pcol[6];
        #pragma unroll
        for (int i = 0; i < 6; i++) {
            Acol[i]  = __ldg(&gA[i*6 + jc]);
            Bmcol[i] = __ldg(&gBm[i*6 + jc]);
            Pcol[i]  = __ldg(&cov0[i*6 + jc]);       // cov0 batch-uniform
            float acc = 0.f;
            #pragma unroll
            for (int k = 0; k < 6; k++) acc += __ldg(&gQt[i*6+k]) * __ldg(&gQt[jc*6+k]);
            Qcol[i] = acc;
        }
        float r00 = 0.f, r01 = 0.f, r02 = 0.f, r11 = 0.f, r12 = 0.f, r22 = 0.f;
        #pragma unroll
        for (int k = 0; k < 3; k++) {
            float a0 = __ldg(&gRt[0*3+k]), a1 = __ldg(&gRt[1*3+k]), a2 = __ldg(&gRt[2*3+k]);
            r00 += a0*a0; r01 += a0*a1; r02 += a0*a2;
            r11 += a1*a1; r12 += a1*a2; r22 += a2*a2;
        }
        float CAcol[3], CBcol[3];
        #pragma unroll
        for (int b = 0; b < 3; b++) {
            float ca = 0.f, cb = 0.f;
            #pragma unroll
            for (int k = 0; k < 6; k++) { ca += sC[b*6+k] * Acol[k]; cb += sC[b*6+k] * Bmcol[k]; }
            CAcol[b] = ca; CBcol[b] = cb;
        }

        for (int t = 0; t < T_STEPS; t++) {
            float AP[6];
            #pragma unroll
            for (int i = 0; i < 6; i++) {
                float acc = 0.f;
                #pragma unroll
                for (int k = 0; k < 6; k++) acc += sA[i*6+k] * Pcol[k];
                AP[i] = acc;
            }
            if (lane < 6) {
                #pragma unroll
                for (int i = 0; i < 6; i++) sAP[i*6 + lane] = AP[i];
            }
            __syncwarp();
            float APr[6];
            #pragma unroll
            for (int k = 0; k < 6; k++) APr[k] = sAP[jc*6 + k];
            float Pp[6];
            #pragma unroll
            for (int c = 0; c < 6; c++) {
                float acc = Qcol[c];
                #pragma unroll
                for (int k = 0; k < 6; k++) acc += APr[k] * sA[c*6+k];
                Pp[c] = acc;
            }
            float CPc[3];
            #pragma unroll
            for (int a = 0; a < 3; a++) {
                float acc = 0.f;
                #pragma unroll
                for (int k = 0; k < 6; k++) acc += sC[a*6+k] * Pp[k];
                CPc[a] = acc;
            }
            if (lane < 6) {
                #pragma unroll
                for (int a = 0; a < 3; a++) sCP[a*6 + lane] = CPc[a];
            }
            __syncwarp();
            float CPall[3][6];
            #pragma unroll
            for (int b = 0; b < 3; b++)
                #pragma unroll
                for (int k = 0; k < 6; k++)
                    CPall[b][k] = sCP[b*6 + k];
            float s00 = r00, s01 = r01, s02 = r02, s11 = r11, s12 = r12, s22 = r22;
            #pragma unroll
            for (int k = 0; k < 6; k++) {
                float c0 = sC[k], c1 = sC[6+k], c2 = sC[12+k];
                s00 += c0 * CPall[0][k]; s01 += c0 * CPall[1][k]; s02 += c0 * CPall[2][k];
                s11 += c1 * CPall[1][k]; s12 += c1 * CPall[2][k]; s22 += c2 * CPall[2][k];
            }
            float i00 = s11*s22 - s12*s12;
            float i01 = s02*s12 - s01*s22;
            float i02 = s01*s12 - s02*s11;
            float i11 = s00*s22 - s02*s02;
            float i12 = s01*s02 - s00*s12;
            float i22 = s00*s11 - s01*s01;
            float rdet = 1.0f / (s00*i00 + s01*i01 + s02*i02);
            i00 *= rdet; i01 *= rdet; i02 *= rdet;
            i11 *= rdet; i12 *= rdet; i22 *= rdet;
            float g0 = i00*CAcol[0] + i01*CAcol[1] + i02*CAcol[2];
            float g1 = i01*CAcol[0] + i11*CAcol[1] + i12*CAcol[2];
            float g2 = i02*CAcol[0] + i12*CAcol[1] + i22*CAcol[2];
            float h0 = i00*CBcol[0] + i01*CBcol[1] + i02*CBcol[2];
            float h1 = i01*CBcol[0] + i11*CBcol[1] + i12*CBcol[2];
            float h2 = i02*CBcol[0] + i12*CBcol[1] + i22*CBcol[2];
            float p0 = i00*CPc[0] + i01*CPc[1] + i02*CPc[2];
            float p1 = i01*CPc[0] + i11*CPc[1] + i12*CPc[2];
            float p2 = i02*CPc[0] + i12*CPc[1] + i22*CPc[2];
            float sv0 = (jc == 0) ? i00 : (jc == 1) ? i01 : i02;
            float sv1 = (jc == 0) ? i01 : (jc == 1) ? i11 : i12;
            float sv2 = (jc == 0) ? i02 : (jc == 1) ? i12 : i22;
            float Mv[6], Nv[6], Kv[6];
            #pragma unroll
            for (int i = 0; i < 6; i++) {
                float c0 = CPall[0][i], c1 = CPall[1][i], c2 = CPall[2][i];
                Mv[i]   = Acol[i]  - (c0*g0 + c1*g1 + c2*g2);
                Nv[i]   = Bmcol[i] - (c0*h0 + c1*h1 + c2*h2);
                Pcol[i] = Pp[i]    - (c0*p0 + c1*p1 + c2*p2);
                Kv[i]   = c0*sv0 + c1*sv1 + c2*sv2;
            }
            if (lane < 6) {
                float2* g = g_coef2 + t * 48;
                #pragma unroll
                for (int p = 0; p < 3; p++) {
                    g[p*16 + lane]     = make_float2(Mv[2*p], Mv[2*p+1]);
                    g[p*16 + 6 + lane] = make_float2(Nv[2*p], Nv[2*p+1]);
                }
                if (lane < 3) {
                    #pragma unroll
                    for (int p = 0; p < 3; p++)
                        g[p*16 + 12 + lane] = make_float2(Kv[2*p], Kv[2*p+1]);
                } else {
                    g[(lane - 3)*16 + 15] = make_float2(0.f, 0.f);   // zero pads
                }
            }
            if ((t & (CHUNK - 1)) == CHUNK - 1) {
                __threadfence();
                __syncwarp();
                if (lane == 0) atomicExch(&g_flag, t + 1);
            }
        }
    } else {
        // ================= CONSUMERS: 2 lanes per batch, multiplier-split =================
        const int tid = threadIdx.x;
        const int r   = tid & 1;                       // lane role within pair
        const int b   = (blockIdx.x - 1) * (BLK/2) + (tid >> 1);

        const float* zbase = meas + (size_t)b * 3;
        const float* ubase = useq + (size_t)b * 6;
        float*       obase = out  + (size_t)b * 6;

        // mult[0..7]: lane0 = {m0..m5, u0, u1}, lane1 = {u2..u5, z0, z1, z2, 0}
        unsigned long long mult[8];
        if (r == 0) {
            const float2* mp = reinterpret_cast<const float2*>(mean0 + (size_t)b * 6);
            float2 a = mp[0], c = mp[1], d = mp[2];
            mult[0] = pack2(a.x, a.x); mult[1] = pack2(a.y, a.y);
            mult[2] = pack2(c.x, c.x); mult[3] = pack2(c.y, c.y);
            mult[4] = pack2(d.x, d.x); mult[5] = pack2(d.y, d.y);
            float2 uu = reinterpret_cast<const float2*>(ubase)[0];
            mult[6] = pack2(uu.x, uu.x); mult[7] = pack2(uu.y, uu.y);
        } else {
            float2 u2 = reinterpret_cast<const float2*>(ubase)[1];
            float2 u4 = reinterpret_cast<const float2*>(ubase)[2];
            float z0 = zbase[0], z1 = zbase[1], z2 = zbase[2];
            mult[0] = pack2(u2.x, u2.x); mult[1] = pack2(u2.y, u2.y);
            mult[2] = pack2(u4.x, u4.x); mult[3] = pack2(u4.y, u4.y);
            mult[4] = pack2(z0, z0); mult[5] = pack2(z1, z1);
            mult[6] = pack2(z2, z2); mult[7] = 0ull;
        }

        #pragma unroll 1
        for (int c = 0; c < T_STEPS / CHUNK; c++) {
            const int target = (c + 1) * CHUNK;
            if (tid == 0) {
                while (((volatile int*)&g_flag)[0] < target) { }
            }
            __syncthreads();
            __threadfence();   // acquire ordering for the __ldcg below
            {
                const float4* src = reinterpret_cast<const float4*>(g_coef2 + (size_t)c * CHUNK * 48);
                float4* dst = reinterpret_cast<float4*>(scf);
                if (tid < CHUNK * 24) dst[tid] = __ldcg(src + tid);
            }
            __syncthreads();

            #pragma unroll
            for (int s = 0; s < CHUNK; s++) {
                const int t = c * CHUNK + s;

                // prefetch next step's lane-specific multipliers
                float2 pfa = make_float2(0.f, 0.f), pfb = make_float2(0.f, 0.f);
                float pz0 = 0.f, pz1 = 0.f, pz2 = 0.f;
                if (t < T_STEPS - 1) {
                    if (r == 0) {
                        pfa = reinterpret_cast<const float2*>(ubase + (size_t)(t+1) * BATCH * 6)[0];
                    } else {
                        const float2* uq = reinterpret_cast<const float2*>(ubase + (size_t)(t+1) * BATCH * 6);
                        pfa = uq[1]; pfb = uq[2];
                        const float* zq = zbase + (size_t)(t+1) * BATCH * 3;
                        pz0 = zq[0]; pz1 = zq[1]; pz2 = zq[2];
                    }
                }

                // partial accumulation: lane r reads its half of each row-pair slice
                unsigned long long full[3];
                #pragma unroll
                for (int p = 0; p < 3; p++) {
                    const ulonglong2* qp =
                        reinterpret_cast<const ulonglong2*>(scf + s * 96 + p * 32 + r * 16);
                    ulonglong2 q0 = qp[0], q1 = qp[1], q2 = qp[2], q3 = qp[3];
                    unsigned long long a_ = fma2(q0.x, mult[0], 0ull);
                    a_ = fma2(q0.y, mult[1], a_);
                    a_ = fma2(q1.x, mult[2], a_);
                    a_ = fma2(q1.y, mult[3], a_);
                    unsigned long long b_ = fma2(q2.x, mult[4], 0ull);
                    b_ = fma2(q2.y, mult[5], b_);
                    b_ = fma2(q3.x, mult[6], b_);
                    b_ = fma2(q3.y, mult[7], b_);
                    unsigned long long acc = add2(a_, b_);
                    // merge with partner lane -> both lanes get the full row-pair
                    unsigned long long other = __shfl_xor_sync(FULLM, acc, 1);
                    full[p] = add2(acc, other);
                }

                // store: lane0 writes pairs 0,1; lane1 writes pair 2
                unsigned long long* oq =
                    reinterpret_cast<unsigned long long*>(obase + (size_t)t * BATCH * 6);
                if (r == 0) { oq[0] = full[0]; oq[1] = full[1]; }
                else        { oq[2] = full[2]; }

                // update multipliers for next step
                if (r == 0) {
                    float lo, hi;
                    unpack2(lo, hi, full[0]); mult[0] = pack2(lo, lo); mult[1] = pack2(hi, hi);
                    unpack2(lo, hi, full[1]); mult[2] = pack2(lo, lo); mult[3] = pack2(hi, hi);
                    unpack2(lo, hi, full[2]); mult[4] = pack2(lo, lo); mult[5] = pack2(hi, hi);
                    if (t < T_STEPS - 1) {
                        mult[6] = pack2(pfa.x, pfa.x); mult[7] = pack2(pfa.y, pfa.y);
                    }
                } else if (t < T_STEPS - 1) {
                    mult[0] = pack2(pfa.x, pfa.x); mult[1] = pack2(pfa.y, pfa.y);
                    mult[2] = pack2(pfb.x, pfb.x); mult[3] = pack2(pfb.y, pfb.y);
                    mult[4] = pack2(pz0, pz0); mult[5] = pack2(pz1, pz1);
                    mult[6] = pack2(pz2, pz2); mult[7] = 0ull;
                }
            }
        }
    }
}

extern "C" void kernel_launch(void* const* d_in, const int* in_sizes, int n_in,
                              void* d_out, int out_size)
{
    const float* meas  = (const float*)d_in[0];   // (T, B, O)
    const float* useq  = (const float*)d_in[1];   // (T, B, U)
    const float* mean0 = (const float*)d_in[2];   // (B, D)
    const float* cov0  = (const float*)d_in[3];   // (B, D, D) -- batch-uniform
    const float* A     = (const float*)d_in[4];   // (D, D)
    const float* Bm    = (const float*)d_in[5];   // (D, U)
    const float* Qt    = (const float*)d_in[6];   // (D, D) lower-tri
    const float* C     = (const float*)d_in[7];   // (O, D)
    const float* Rt    = (const float*)d_in[8];   // (O, O) lower-tri
    float* out = (float*)d_out;                   // (T, B, D)

    reset_kernel<<<1, 1>>>();
    fused_kernel<<<NCBLK + 1, BLK>>>(meas, useq, mean0, cov0, A, Bm, Qt, C, Rt, out);
}